// round 2
// baseline (speedup 1.0000x reference)
#include <cuda_runtime.h>
#include <cuda_fp16.h>
#include <cstdint>

constexpr int MTOT = 65536;        // 4096*16 rows
constexpr int KD   = 512;

// ---- scratch (allocation-free rule: device globals) ----
__device__ __half g_xh[(size_t)MTOT * 512];
__device__ __half g_wq[512 * 1536];
__device__ __half g_wo[512 * 512];
__device__ __half g_qkv[(size_t)MTOT * 1536];
__device__ __half g_at[(size_t)MTOT * 512];

__device__ __forceinline__ uint32_t sp(const void* p) {
    return (uint32_t)__cvta_generic_to_shared(p);
}

#define CPA(d, s) asm volatile("cp.async.cg.shared.global [%0],[%1],16;" :: "r"(sp(d)), "l"(s))

// ---------------------------------------------------------------------------
// K0: fp32 -> fp16 conversion of x and both weights (vectorized)
// ---------------------------------------------------------------------------
__global__ void k_convert(const float4* __restrict__ x, const float4* __restrict__ wq,
                          const float4* __restrict__ wo) {
    size_t i = (size_t)blockIdx.x * 256 + threadIdx.x;   // float4 index
    if (i < (size_t)MTOT * 128) {
        float4 v = x[i];
        __half2* d = (__half2*)&g_xh[i * 4];
        d[0] = __floats2half2_rn(v.x, v.y); d[1] = __floats2half2_rn(v.z, v.w);
    }
    if (i < 512 * 384) {
        float4 v = wq[i];
        __half2* d = (__half2*)&g_wq[i * 4];
        d[0] = __floats2half2_rn(v.x, v.y); d[1] = __floats2half2_rn(v.z, v.w);
    }
    if (i < 512 * 128) {
        float4 v = wo[i];
        __half2* d = (__half2*)&g_wo[i * 4];
        d[0] = __floats2half2_rn(v.x, v.y); d[1] = __floats2half2_rn(v.z, v.w);
    }
}

// ---------------------------------------------------------------------------
// GEMM: C[M,N] = A[M,512] * B[512,N], fp16 in, fp32 accum.
// Block 128x128, 8 warps (2m x 4n), warp tile 64x32, mma.m16n8k16.
// EPIH=1: fp16 output; EPIH=0: fp32 output.
// ---------------------------------------------------------------------------
template<int EPIH>
__global__ __launch_bounds__(256) void k_gemm(const __half* __restrict__ A,
                                              const __half* __restrict__ B,
                                              void* __restrict__ Cv, int N) {
    __shared__ __half As[2][128][40];   // pad 32->40: conflict-free ldmatrix
    __shared__ __half Bs[2][32][136];   // pad 128->136
    const int t = threadIdx.x, lane = t & 31, w = t >> 5;
    const int wm = w >> 2, wn = w & 3;
    const size_t row0 = (size_t)blockIdx.y * 128;
    const int col0 = blockIdx.x * 128;

    float c[4][4][4] = {};

#define LOADTILE(buf, kt) do {                                                    \
    int u = t, r = u >> 2, kc = u & 3;                                            \
    CPA(&As[buf][r][kc * 8], &A[(row0 + r) * 512 + (kt) * 32 + kc * 8]);          \
    u = t + 256; r = u >> 2; kc = u & 3;                                          \
    CPA(&As[buf][r][kc * 8], &A[(row0 + r) * 512 + (kt) * 32 + kc * 8]);          \
    u = t; int kr = u >> 4, nc = u & 15;                                          \
    CPA(&Bs[buf][kr][nc * 8], &B[(size_t)((kt) * 32 + kr) * N + col0 + nc * 8]);  \
    u = t + 256; kr = u >> 4; nc = u & 15;                                        \
    CPA(&Bs[buf][kr][nc * 8], &B[(size_t)((kt) * 32 + kr) * N + col0 + nc * 8]);  \
    asm volatile("cp.async.commit_group;"); } while (0)

    LOADTILE(0, 0);

    for (int kt = 0; kt < 16; ++kt) {
        if (kt < 15) {
            LOADTILE((kt + 1) & 1, kt + 1);
            asm volatile("cp.async.wait_group 1;");
        } else {
            asm volatile("cp.async.wait_group 0;");
        }
        __syncthreads();
        const int buf = kt & 1;

        #pragma unroll
        for (int ks = 0; ks < 2; ++ks) {
            const int k0 = ks * 16;
            uint32_t a[4][4], b[2][4];
            #pragma unroll
            for (int mi = 0; mi < 4; ++mi) {
                const __half* p = &As[buf][wm * 64 + mi * 16 + (lane & 15)][k0 + 8 * (lane >> 4)];
                asm volatile("ldmatrix.sync.aligned.m8n8.x4.shared.b16 {%0,%1,%2,%3},[%4];"
                             : "=r"(a[mi][0]), "=r"(a[mi][1]), "=r"(a[mi][2]), "=r"(a[mi][3])
                             : "r"(sp(p)));
            }
            #pragma unroll
            for (int nj = 0; nj < 2; ++nj) {
                const __half* p = &Bs[buf][k0 + (lane & 15)][wn * 32 + nj * 16 + 8 * (lane >> 4)];
                asm volatile("ldmatrix.sync.aligned.m8n8.x4.trans.shared.b16 {%0,%1,%2,%3},[%4];"
                             : "=r"(b[nj][0]), "=r"(b[nj][1]), "=r"(b[nj][2]), "=r"(b[nj][3])
                             : "r"(sp(p)));
            }
            #pragma unroll
            for (int mi = 0; mi < 4; ++mi)
                #pragma unroll
                for (int ni = 0; ni < 4; ++ni) {
                    const uint32_t b0 = b[ni >> 1][(ni & 1) * 2], b1 = b[ni >> 1][(ni & 1) * 2 + 1];
                    asm volatile(
                        "mma.sync.aligned.m16n8k16.row.col.f32.f16.f16.f32 "
                        "{%0,%1,%2,%3},{%4,%5,%6,%7},{%8,%9},{%0,%1,%2,%3};"
                        : "+f"(c[mi][ni][0]), "+f"(c[mi][ni][1]), "+f"(c[mi][ni][2]), "+f"(c[mi][ni][3])
                        : "r"(a[mi][0]), "r"(a[mi][1]), "r"(a[mi][2]), "r"(a[mi][3]),
                          "r"(b0), "r"(b1));
                }
        }
        __syncthreads();
    }
#undef LOADTILE

    const int qr = lane >> 2, qc = lane & 3;
    #pragma unroll
    for (int mi = 0; mi < 4; ++mi)
        #pragma unroll
        for (int ni = 0; ni < 4; ++ni) {
            const size_t r = row0 + wm * 64 + mi * 16 + qr;
            const int cc = col0 + wn * 32 + ni * 8 + qc * 2;
            if (EPIH) {
                __half* C = (__half*)Cv;
                *(__half2*)&C[r * N + cc]       = __floats2half2_rn(c[mi][ni][0], c[mi][ni][1]);
                *(__half2*)&C[(r + 8) * N + cc] = __floats2half2_rn(c[mi][ni][2], c[mi][ni][3]);
            } else {
                float* C = (float*)Cv;
                *(float2*)&C[r * N + cc]       = make_float2(c[mi][ni][0], c[mi][ni][1]);
                *(float2*)&C[(r + 8) * N + cc] = make_float2(c[mi][ni][2], c[mi][ni][3]);
            }
        }
}

// ---------------------------------------------------------------------------
// K2: per-batch attention. Block = 1 batch (16 frames), 256 threads, 8 warps
// (one per head). Loads qkv fp16 -> fp32 smem, q softmax over d (*SCALE),
// k softmax over n, s = q k^T (16x16), o = s v (16x64), writes fp16 attn.
// ---------------------------------------------------------------------------
constexpr int RST = 517;                          // smem row stride (conflict-free)
constexpr int ATTN_SMEM = (3 * 16 * RST + 8 * 16 * 17) * 4;

__global__ __launch_bounds__(256) void k_attn() {
    extern __shared__ float sm[];
    float* s_q = sm;
    float* s_k = s_q + 16 * RST;
    float* s_v = s_k + 16 * RST;
    float* s_s = s_v + 16 * RST;                  // [8][16][17]

    const int t = threadIdx.x, lane = t & 31, h = t >> 5;
    const size_t rowB = (size_t)blockIdx.x * 16;

    // load 16 x 1536 fp16 -> fp32 smem
    #pragma unroll
    for (int i = 0; i < 12; ++i) {
        const int u = t + 256 * i;                // uint4 id, 0..3071
        const int n = u / 192, c8 = u % 192;
        uint4 raw = *(const uint4*)&g_qkv[(rowB + n) * 1536 + c8 * 8];
        float* dst = (c8 < 64)  ? (s_q + n * RST + c8 * 8)
                   : (c8 < 128) ? (s_k + n * RST + (c8 - 64) * 8)
                                : (s_v + n * RST + (c8 - 128) * 8);
        const __half2* hp = (const __half2*)&raw;
        #pragma unroll
        for (int j = 0; j < 4; ++j) {
            float2 f = __half22float2(hp[j]);
            dst[2 * j] = f.x; dst[2 * j + 1] = f.y;
        }
    }
    __syncthreads();

    // q softmax over d=64, * SCALE(0.125)
    if (t < 128) {
        const int n = t & 15, hh = t >> 4;
        float* p = s_q + n * RST + hh * 64;
        float mx = -1e30f;
        #pragma unroll 8
        for (int j = 0; j < 64; ++j) mx = fmaxf(mx, p[j]);
        float s = 0.f;
        #pragma unroll 8
        for (int j = 0; j < 64; ++j) { float e = __expf(p[j] - mx); p[j] = e; s += e; }
        const float inv = 0.125f / s;
        #pragma unroll 8
        for (int j = 0; j < 64; ++j) p[j] *= inv;
    }
    // k softmax over n=16 (columns); each thread owns 2 of 512 columns
    #pragma unroll
    for (int rep = 0; rep < 2; ++rep) {
        float* p = s_k + t + rep * 256;
        float mx = -1e30f;
        #pragma unroll
        for (int n = 0; n < 16; ++n) mx = fmaxf(mx, p[n * RST]);
        float s = 0.f;
        #pragma unroll
        for (int n = 0; n < 16; ++n) { float e = __expf(p[n * RST] - mx); p[n * RST] = e; s += e; }
        const float inv = 1.f / s;
        #pragma unroll
        for (int n = 0; n < 16; ++n) p[n * RST] *= inv;
    }
    __syncthreads();

    // s = q k^T per head: lane -> 4 n-rows x 2 m-cols
    {
        const int lr = lane >> 3, lc = lane & 7;
        float sa[4][2] = {};
        const float* qb = s_q + h * 64;
        const float* kb = s_k + h * 64;
        #pragma unroll 8
        for (int d = 0; d < 64; ++d) {
            const float k0v = kb[(lc * 2) * RST + d], k1v = kb[(lc * 2 + 1) * RST + d];
            #pragma unroll
            for (int i = 0; i < 4; ++i) {
                const float qv = qb[(lr * 4 + i) * RST + d];
                sa[i][0] += qv * k0v; sa[i][1] += qv * k1v;
            }
        }
        #pragma unroll
        for (int i = 0; i < 4; ++i) {
            s_s[h * 272 + (lr * 4 + i) * 17 + lc * 2]     = sa[i][0];
            s_s[h * 272 + (lr * 4 + i) * 17 + lc * 2 + 1] = sa[i][1];
        }
    }
    __syncwarp();

    // o = s v per head: lane -> 4 n-rows x 8 e-cols
    {
        const int nb = lane >> 3, eb = lane & 7;
        float o[4][8] = {};
        #pragma unroll
        for (int m = 0; m < 16; ++m) {
            float sv[4];
            #pragma unroll
            for (int i = 0; i < 4; ++i) sv[i] = s_s[h * 272 + (nb * 4 + i) * 17 + m];
            const float* vb = s_v + m * RST + h * 64 + eb * 8;
            #pragma unroll
            for (int j = 0; j < 8; ++j) {
                const float vv = vb[j];
                #pragma unroll
                for (int i = 0; i < 4; ++i) o[i][j] += sv[i] * vv;
            }
        }
        #pragma unroll
        for (int i = 0; i < 4; ++i) {
            __half2 pk[4];
            #pragma unroll
            for (int j = 0; j < 4; ++j) pk[j] = __floats2half2_rn(o[i][2 * j], o[i][2 * j + 1]);
            *(uint4*)&g_at[(rowB + nb * 4 + i) * 512 + h * 64 + eb * 8] = *(uint4*)pk;
        }
    }
}

// ---------------------------------------------------------------------------
extern "C" void kernel_launch(void* const* d_in, const int* in_sizes, int n_in,
                              void* d_out, int out_size) {
    const float* x  = (const float*)d_in[0];
    const float* wq = (const float*)d_in[1];
    const float* wo = (const float*)d_in[2];

    void *pxh, *pwq, *pwo, *pqkv, *pat;
    cudaGetSymbolAddress(&pxh, g_xh);
    cudaGetSymbolAddress(&pwq, g_wq);
    cudaGetSymbolAddress(&pwo, g_wo);
    cudaGetSymbolAddress(&pqkv, g_qkv);
    cudaGetSymbolAddress(&pat, g_at);
    cudaFuncSetAttribute(k_attn, cudaFuncAttributeMaxDynamicSharedMemorySize, ATTN_SMEM);

    k_convert<<<32768, 256>>>((const float4*)x, (const float4*)wq, (const float4*)wo);
    k_gemm<1><<<dim3(12, 512), 256>>>((const __half*)pxh, (const __half*)pwq, pqkv, 1536);
    k_attn<<<4096, 256, ATTN_SMEM>>>();
    k_gemm<0><<<dim3(4, 512), 256>>>((const __half*)pat, (const __half*)pwo, d_out, 512);
}